// round 1
// baseline (speedup 1.0000x reference)
#include <cuda_runtime.h>

// Normalized ordinal weights: [128 channels][4 taps], laid out so that
// channel c's 4 taps are one float4.
__device__ float g_w[128 * 4];

__global__ void normw_kernel(const float* __restrict__ w) {
    int c = threadIdx.x;
    if (c < 128) {
        float a = w[c * 4 + 0];
        float b = w[c * 4 + 1];
        float d = w[c * 4 + 2];
        float e = w[c * 4 + 3];
        // w * (w >= 0)
        a = (a >= 0.0f) ? a : 0.0f;
        b = (b >= 0.0f) ? b : 0.0f;
        d = (d >= 0.0f) ? d : 0.0f;
        e = (e >= 0.0f) ? e : 0.0f;
        float inv = 1.0f / (a + b + d + e);
        g_w[c * 4 + 0] = a * inv;
        g_w[c * 4 + 1] = b * inv;
        g_w[c * 4 + 2] = d * inv;
        g_w[c * 4 + 3] = e * inv;
    }
}

// Odd-even transposition sort (descending) of 4 values, then weighted sum.
// Network for n=4 (matching reference loop `for i in range(4)`):
//   i=0: (0,1),(2,3)   i=1: (1,2)   i=2: (0,1),(2,3)   i=3: (1,2)
__device__ __forceinline__ float sort4_dot(float s0, float s1, float s2, float s3,
                                           float4 w) {
    float t;
    // round 0
    t = fmaxf(s0, s1); s1 = fminf(s0, s1); s0 = t;
    t = fmaxf(s2, s3); s3 = fminf(s2, s3); s2 = t;
    // round 1
    t = fmaxf(s1, s2); s2 = fminf(s1, s2); s1 = t;
    // round 2
    t = fmaxf(s0, s1); s1 = fminf(s0, s1); s0 = t;
    t = fmaxf(s2, s3); s3 = fminf(s2, s3); s2 = t;
    // round 3
    t = fmaxf(s1, s2); s2 = fminf(s1, s2); s1 = t;
    return s0 * w.x + s1 * w.y + s2 * w.z + s3 * w.w;
}

// Geometry constants
#define N_   32
#define H_   112
#define W_   112
#define C_   128
#define HO_  56
#define WO_  56
#define C4_  (C_ / 4)            // 32 float4 per channel row
#define ROW4 (W_ * C4_)          // input row stride in float4 units = 3584
#define NV   (N_ * HO_ * WO_ * C4_)  // total output float4 = 3,211,264

__global__ void __launch_bounds__(256)
ordpool_kernel(const float4* __restrict__ x, float4* __restrict__ out) {
    int v = blockIdx.x * blockDim.x + threadIdx.x;
    if (v >= NV) return;

    int c4 = v & (C4_ - 1);
    int r  = v >> 5;             // log2(C4_) = 5
    int wo = r % WO_;
    r /= WO_;
    int ho = r % HO_;
    int n  = r / HO_;

    int base = ((n * H_ + 2 * ho) * W_ + 2 * wo) * C4_ + c4;

    // 4 window positions, issued back-to-back for MLP
    float4 a00 = x[base];
    float4 a01 = x[base + C4_];
    float4 a10 = x[base + ROW4];
    float4 a11 = x[base + ROW4 + C4_];

    const float4* __restrict__ gw4 = (const float4*)g_w;
    float4 w0 = gw4[4 * c4 + 0];
    float4 w1 = gw4[4 * c4 + 1];
    float4 w2 = gw4[4 * c4 + 2];
    float4 w3 = gw4[4 * c4 + 3];

    float4 o;
    o.x = sort4_dot(a00.x, a01.x, a10.x, a11.x, w0);
    o.y = sort4_dot(a00.y, a01.y, a10.y, a11.y, w1);
    o.z = sort4_dot(a00.z, a01.z, a10.z, a11.z, w2);
    o.w = sort4_dot(a00.w, a01.w, a10.w, a11.w, w3);

    out[v] = o;
}

extern "C" void kernel_launch(void* const* d_in, const int* in_sizes, int n_in,
                              void* d_out, int out_size) {
    const float* x = (const float*)d_in[0];
    const float* w = (const float*)d_in[1];
    float* out = (float*)d_out;

    normw_kernel<<<1, 128>>>(w);
    ordpool_kernel<<<(NV + 255) / 256, 256>>>((const float4*)x, (float4*)out);
}